// round 1
// baseline (speedup 1.0000x reference)
#include <cuda_runtime.h>
#include <cstdint>

// Problem constants
#define BATCH 8192
#define MDIM  512
#define NDIM  2048

// GEMM tiling
#define TB 128   // batch-tile
#define TP 128   // output-col tile
#define TK 16    // k tile

// Scratch for residual r [BATCH, MDIM] (16 MB). Static device array per rules.
__device__ __align__(128) float g_r[(size_t)BATCH * MDIM];

// ---------------------------------------------------------------------------
// Generic fp32 SGEMM: C[b,p] = epilogue( sum_k X[b,k] * W[k,p] )
//   MODE 0: out = mu[muidx] * acc                       (init: x0 = mu0 * y@A)
//   MODE 1: out = acc - aux[b,p]                        (residual: r = x@W - y)
//   MODE 2: out = aux[b,p] - mu[muidx] * acc            (update:  v = x - mu*(r@A))
// X: [B, K] row-major (ld=K). W: [K, P] row-major (ld=P). out/aux: [B, P] (ld=P).
// ---------------------------------------------------------------------------
template<int MODE>
__global__ __launch_bounds__(256, 2)
void gemm_kernel(const float* __restrict__ X, const float* __restrict__ W,
                 float* __restrict__ out, const float* __restrict__ aux,
                 const float* __restrict__ mu, int muidx, int K, int P)
{
    __shared__ float Xs[TK][TB + 4];   // +4 pad: conflict-free transposed stores
    __shared__ float Ws[TK][TP];

    const int tid  = threadIdx.x;
    const int b0   = blockIdx.x * TB;
    const int p0   = blockIdx.y * TP;
    const int trow = tid >> 4;         // 0..15
    const int tcol = tid & 15;         // 0..15
    const int r0   = trow * 8;
    const int c0   = tcol * 8;

    float acc[8][8];
    #pragma unroll
    for (int i = 0; i < 8; i++)
        #pragma unroll
        for (int j = 0; j < 8; j++) acc[i][j] = 0.f;

    for (int kk = 0; kk < K; kk += TK) {
        // Load X tile [TB rows x TK cols] -> Xs transposed.  512 float4, 2/thread.
        // Load W tile [TK rows x TP cols] -> Ws direct.      512 float4, 2/thread.
        #pragma unroll
        for (int l = 0; l < 2; l++) {
            int f = tid + l * 256;
            int xr = f >> 2, xc4 = f & 3;
            float4 xv = *reinterpret_cast<const float4*>(
                X + (size_t)(b0 + xr) * K + kk + xc4 * 4);
            Xs[xc4 * 4 + 0][xr] = xv.x;
            Xs[xc4 * 4 + 1][xr] = xv.y;
            Xs[xc4 * 4 + 2][xr] = xv.z;
            Xs[xc4 * 4 + 3][xr] = xv.w;

            int wk = f >> 5, wc4 = f & 31;
            float4 wv = *reinterpret_cast<const float4*>(
                W + (size_t)(kk + wk) * P + p0 + wc4 * 4);
            *reinterpret_cast<float4*>(&Ws[wk][wc4 * 4]) = wv;
        }
        __syncthreads();

        #pragma unroll
        for (int k = 0; k < TK; k++) {
            float a[8], bb[8];
            #pragma unroll
            for (int i = 0; i < 8; i++) a[i]  = Xs[k][r0 + i];
            #pragma unroll
            for (int j = 0; j < 8; j++) bb[j] = Ws[k][c0 + j];
            #pragma unroll
            for (int i = 0; i < 8; i++)
                #pragma unroll
                for (int j = 0; j < 8; j++)
                    acc[i][j] = fmaf(a[i], bb[j], acc[i][j]);
        }
        __syncthreads();
    }

    float scale = 0.f;
    if (MODE == 0 || MODE == 2) scale = mu[muidx];

    #pragma unroll
    for (int i = 0; i < 8; i++) {
        const size_t rowoff = (size_t)(b0 + r0 + i) * P + p0 + c0;
        #pragma unroll
        for (int j = 0; j < 8; j++) {
            float a = acc[i][j];
            float o;
            if (MODE == 0)      o = scale * a;
            else if (MODE == 1) o = a - aux[rowoff + j];
            else                o = aux[rowoff + j] - scale * a;
            out[rowoff + j] = o;
        }
    }
}

// ---------------------------------------------------------------------------
// Per-row shrink: find thr = kth-largest |v| (exact, via 4x8-bit radix select
// on float bit patterns), then x = (|v|>=thr) ? v : beta*softshrink(v/beta,1).
// One CTA (256 threads) per row of 2048.
// ---------------------------------------------------------------------------
__global__ void shrink_kernel(float* __restrict__ x, const float* __restrict__ beta,
                              int bidx, int kth)
{
    __shared__ float vsh[NDIM];
    __shared__ int   hist[256];
    __shared__ int   s_sel;
    __shared__ int   s_need;

    const int tid = threadIdx.x;
    float* v = x + (size_t)blockIdx.x * NDIM;

    #pragma unroll
    for (int i = tid; i < NDIM; i += 256) vsh[i] = v[i];
    __syncthreads();

    unsigned int prefix = 0u;
    int need = kth;   // 1-based rank from the top

    #pragma unroll
    for (int pass = 0; pass < 4; pass++) {
        const int shift = 24 - 8 * pass;
        const unsigned int himask = (pass == 0) ? 0u : (0xFFFFFFFFu << (shift + 8));

        hist[tid] = 0;
        __syncthreads();
        for (int i = tid; i < NDIM; i += 256) {
            unsigned int key = __float_as_uint(fabsf(vsh[i]));
            if ((key & himask) == prefix)
                atomicAdd(&hist[(key >> shift) & 255], 1);
        }
        __syncthreads();
        if (tid == 0) {
            int cum = 0, d = 255;
            for (; d > 0; d--) { cum += hist[d]; if (cum >= need) break; }
            if (cum < need) { cum += hist[0]; d = 0; }   // falls in bin 0
            s_sel  = d;
            s_need = need - (cum - hist[d]);             // rank within chosen bin
        }
        __syncthreads();
        prefix |= ((unsigned int)s_sel) << shift;
        need = s_need;
        __syncthreads();
    }

    const float thr = __uint_as_float(prefix);
    const float b   = beta[bidx];

    for (int i = tid; i < NDIM; i += 256) {
        float val = vsh[i];
        float av  = fabsf(val);
        // Replicate JAX: beta * sign(u) * max(|u|-1, 0), u = val/beta
        float u    = val / b;
        float mag  = fmaxf(fabsf(u) - 1.0f, 0.0f);
        float soft = b * copysignf(mag, u);
        v[i] = (av >= thr) ? val : soft;
    }
}

// ---------------------------------------------------------------------------
extern "C" void kernel_launch(void* const* d_in, const int* in_sizes, int n_in,
                              void* d_out, int out_size)
{
    const float* y    = (const float*)d_in[0];   // [8192, 512]
    const float* A    = (const float*)d_in[1];   // [512, 2048]
    const float* W    = (const float*)d_in[2];   // [2048, 512]  (= A^T)
    const float* beta = (const float*)d_in[3];   // [6]
    const float* mu   = (const float*)d_in[4];   // [6]
    float* x = (float*)d_out;                    // [8192, 2048]

    void* rp = nullptr;
    cudaGetSymbolAddress(&rp, g_r);
    float* r = (float*)rp;

    const dim3 blk(256);
    const dim3 gN(BATCH / TB, NDIM / TP);   // (64, 16)  P=2048 GEMMs
    const dim3 gM(BATCH / TB, MDIM / TP);   // (64, 4)   P=512  GEMM

    // idx = int(min(0.012*t, 0.12) * 2048), t = 1..5
    const int kth[6] = {0, 24, 49, 73, 98, 122};

    // x0 = mu[0] * (y @ A)   (t=0 shrink is identity: thr=0)
    gemm_kernel<0><<<gN, blk>>>(y, A, x, nullptr, mu, 0, MDIM, NDIM);

    for (int t = 1; t <= 5; t++) {
        // r = x @ W - y        [B, M]
        gemm_kernel<1><<<gM, blk>>>(x, W, r, y, mu, t, NDIM, MDIM);
        // v = x - mu[t]*(r @ A)  [B, N]  (in-place into x buffer)
        gemm_kernel<2><<<gN, blk>>>(r, A, x, x, mu, t, MDIM, NDIM);
        // x = shrink(v, beta[t], t)
        shrink_kernel<<<BATCH, blk>>>(x, beta, t, kth[t]);
    }
}

// round 3
// speedup vs baseline: 3.3045x; 3.3045x over previous
#include <cuda_runtime.h>
#include <cuda_bf16.h>
#include <cstdint>

#define BATCH 8192
#define MDIM  512
#define NDIM  2048

typedef __nv_bfloat16 bf16;

// ---------------- static device scratch (no allocs allowed) ----------------
__device__ __align__(256) bf16 g_xh[(size_t)BATCH * NDIM];
__device__ __align__(256) bf16 g_xl[(size_t)BATCH * NDIM];
__device__ __align__(256) bf16 g_rh[(size_t)BATCH * MDIM];
__device__ __align__(256) bf16 g_rl[(size_t)BATCH * MDIM];
__device__ __align__(256) bf16 g_yh[(size_t)BATCH * MDIM];
__device__ __align__(256) bf16 g_yl[(size_t)BATCH * MDIM];
__device__ __align__(256) bf16 g_Ah[(size_t)MDIM * NDIM];
__device__ __align__(256) bf16 g_Al[(size_t)MDIM * NDIM];
__device__ __align__(256) bf16 g_Wh[(size_t)NDIM * MDIM];
__device__ __align__(256) bf16 g_Wl[(size_t)NDIM * MDIM];

// ---------------- PTX helpers (base-ISA only: sm_80-class) ----------------
__device__ __forceinline__ uint32_t smem_u32(const void* p) {
    uint32_t a;
    asm("{ .reg .u64 t; cvta.to.shared.u64 t, %1; cvt.u32.u64 %0, t; }" : "=r"(a) : "l"(p));
    return a;
}
__device__ __forceinline__ void cpa16(uint32_t dst, const void* src) {
    asm volatile("cp.async.cg.shared.global [%0], [%1], 16;" :: "r"(dst), "l"(src));
}
__device__ __forceinline__ void cpa_commit() { asm volatile("cp.async.commit_group;" ::: "memory"); }
template<int N> __device__ __forceinline__ void cpa_wait() {
    asm volatile("cp.async.wait_group %0;" :: "n"(N) : "memory");
}
__device__ __forceinline__ void ldm_x4(uint32_t* r, uint32_t addr) {
    asm volatile("ldmatrix.sync.aligned.m8n8.x4.shared.b16 {%0,%1,%2,%3}, [%4];"
        : "=r"(r[0]), "=r"(r[1]), "=r"(r[2]), "=r"(r[3]) : "r"(addr));
}
__device__ __forceinline__ void ldm_x2(uint32_t* r, uint32_t addr) {
    asm volatile("ldmatrix.sync.aligned.m8n8.x2.shared.b16 {%0,%1}, [%2];"
        : "=r"(r[0]), "=r"(r[1]) : "r"(addr));
}
__device__ __forceinline__ void mma_bf16(float* d, const uint32_t* a, const uint32_t* b) {
    asm volatile("mma.sync.aligned.m16n8k16.row.col.f32.bf16.bf16.f32 "
        "{%0,%1,%2,%3}, {%4,%5,%6,%7}, {%8,%9}, {%0,%1,%2,%3};"
        : "+f"(d[0]), "+f"(d[1]), "+f"(d[2]), "+f"(d[3])
        : "r"(a[0]), "r"(a[1]), "r"(a[2]), "r"(a[3]), "r"(b[0]), "r"(b[1]));
}

// ---------------- fp32 -> bf16 hi/lo split ----------------
__global__ void split_kernel(const float* __restrict__ s, bf16* __restrict__ h,
                             bf16* __restrict__ l, int n4) {
    int i = blockIdx.x * 256 + threadIdx.x;
    if (i >= n4) return;
    float4 v = reinterpret_cast<const float4*>(s)[i];
    bf16 h0 = __float2bfloat16(v.x), h1 = __float2bfloat16(v.y);
    bf16 h2 = __float2bfloat16(v.z), h3 = __float2bfloat16(v.w);
    __nv_bfloat162 hp0{h0, h1}, hp1{h2, h3};
    __nv_bfloat162 lp0{__float2bfloat16(v.x - __bfloat162float(h0)),
                       __float2bfloat16(v.y - __bfloat162float(h1))};
    __nv_bfloat162 lp1{__float2bfloat16(v.z - __bfloat162float(h2)),
                       __float2bfloat16(v.w - __bfloat162float(h3))};
    reinterpret_cast<__nv_bfloat162*>(h)[i * 2 + 0] = hp0;
    reinterpret_cast<__nv_bfloat162*>(h)[i * 2 + 1] = hp1;
    reinterpret_cast<__nv_bfloat162*>(l)[i * 2 + 0] = lp0;
    reinterpret_cast<__nv_bfloat162*>(l)[i * 2 + 1] = lp1;
}

// ---------------- HMMA split-bf16 GEMM ----------------
// C[b,p] = sum_k X[b,k]*Wm[p,k]  (both K-major). 3-product split: hh + hl + lh.
// MODE 0: f = mu*acc         -> outf + splits
// MODE 1: f = acc - aux      -> splits only
// MODE 2: f = aux - mu*acc   -> outf only
#define PITCH 80                       // 32 bf16 (64B) + 16B pad per row
#define TILE_B (128 * PITCH)           // 10240 B per tile
#define STAGE_B (4 * TILE_B)           // Xh, Xl, Wh, Wl
#define SMEM_B (2 * STAGE_B)           // 81920 B

template<int MODE>
__global__ __launch_bounds__(256, 1)
void mma_gemm(const bf16* __restrict__ Xh, const bf16* __restrict__ Xl,
              const bf16* __restrict__ Bh, const bf16* __restrict__ Bl,
              int K, int P,
              float* __restrict__ outf, bf16* __restrict__ outh, bf16* __restrict__ outl,
              const float* __restrict__ aux, const float* __restrict__ mu, int muidx)
{
    extern __shared__ char smem[];
    const uint32_t sb = smem_u32(smem);
    const int tid = threadIdx.x, lane = tid & 31, wid = tid >> 5;
    const int wr = wid >> 2, wc = wid & 3;          // 2x4 warp grid
    const int b0 = blockIdx.x * 128, p0 = blockIdx.y * 128;

    float acc[4][4][4];
    #pragma unroll
    for (int i = 0; i < 4; i++)
        #pragma unroll
        for (int j = 0; j < 4; j++)
            #pragma unroll
            for (int q = 0; q < 4; q++) acc[i][j][q] = 0.f;

    const int nch = K >> 5;   // KC = 32

    auto load_stage = [&](int s, int c) {
        const int k0 = c * 32;
        const uint32_t st = sb + s * STAGE_B;
        const bf16* srcs[4] = { Xh + (size_t)b0 * K + k0, Xl + (size_t)b0 * K + k0,
                                Bh + (size_t)p0 * K + k0, Bl + (size_t)p0 * K + k0 };
        #pragma unroll
        for (int t = 0; t < 4; t++) {
            const uint32_t tb = st + t * TILE_B;
            const bf16* g = srcs[t];
            #pragma unroll
            for (int l = 0; l < 2; l++) {
                int id = tid + l * 256;               // 0..511
                int row = id >> 2, ch = id & 3;
                cpa16(tb + row * PITCH + ch * 16, g + (size_t)row * K + ch * 8);
            }
        }
        cpa_commit();
    };

    load_stage(0, 0);
    if (nch > 1) load_stage(1, 1);

    for (int c = 0; c < nch; c++) {
        const int s = c & 1;
        if (c + 1 < nch) cpa_wait<1>(); else cpa_wait<0>();
        __syncthreads();

        const uint32_t xs = sb + s * STAGE_B;
        const uint32_t ws = xs + 2 * TILE_B;
        #pragma unroll
        for (int ks = 0; ks < 2; ks++) {
            const int kb = ks * 32;                  // byte offset of k16 step
            uint32_t ah[4][4], al[4][4], bh[4][2], bl[4][2];
            #pragma unroll
            for (int mi = 0; mi < 4; mi++) {
                uint32_t a = xs + (uint32_t)(wr * 64 + mi * 16 + (lane & 15)) * PITCH
                           + kb + ((lane >> 4) << 4);
                ldm_x4(ah[mi], a);
                ldm_x4(al[mi], a + TILE_B);
            }
            #pragma unroll
            for (int ni = 0; ni < 4; ni++) {
                uint32_t a = ws + (uint32_t)(wc * 32 + ni * 8 + (lane & 7)) * PITCH
                           + kb + (((lane >> 3) & 1) << 4);
                ldm_x2(bh[ni], a);
                ldm_x2(bl[ni], a + TILE_B);
            }
            #pragma unroll
            for (int mi = 0; mi < 4; mi++)
                #pragma unroll
                for (int ni = 0; ni < 4; ni++) {
                    mma_bf16(acc[mi][ni], ah[mi], bh[ni]);
                    mma_bf16(acc[mi][ni], ah[mi], bl[ni]);
                    mma_bf16(acc[mi][ni], al[mi], bh[ni]);
                }
        }
        __syncthreads();
        if (c + 2 < nch) load_stage(s, c + 2);
    }

    // ---------------- epilogue ----------------
    const float m = (MODE != 1) ? __ldg(mu + muidx) : 0.f;
    const int rbase = b0 + wr * 64 + (lane >> 2);
    const int cbase = p0 + wc * 32 + (lane & 3) * 2;

    #pragma unroll
    for (int mi = 0; mi < 4; mi++) {
        #pragma unroll
        for (int h = 0; h < 2; h++) {
            const int row = rbase + mi * 16 + h * 8;
            #pragma unroll
            for (int ni = 0; ni < 4; ni++) {
                const size_t off = (size_t)row * P + cbase + ni * 8;
                float v0 = acc[mi][ni][h * 2], v1 = acc[mi][ni][h * 2 + 1];
                if (MODE == 0) { v0 *= m; v1 *= m; }
                else {
                    float2 a2 = *reinterpret_cast<const float2*>(aux + off);
                    if (MODE == 1) { v0 -= a2.x; v1 -= a2.y; }
                    else { v0 = a2.x - m * v0; v1 = a2.y - m * v1; }
                }
                if (MODE == 0 || MODE == 2)
                    *reinterpret_cast<float2*>(outf + off) = make_float2(v0, v1);
                if (MODE == 0 || MODE == 1) {
                    bf16 h0 = __float2bfloat16(v0), h1 = __float2bfloat16(v1);
                    __nv_bfloat162 hp{h0, h1};
                    __nv_bfloat162 lp{__float2bfloat16(v0 - __bfloat162float(h0)),
                                      __float2bfloat16(v1 - __bfloat162float(h1))};
                    *reinterpret_cast<__nv_bfloat162*>(outh + off) = hp;
                    *reinterpret_cast<__nv_bfloat162*>(outl + off) = lp;
                }
            }
        }
    }
}

// ---------------- shrink: exact kth-largest via bitwise binary search ----------------
__global__ __launch_bounds__(256, 4)
void shrink2(float* __restrict__ x, bf16* __restrict__ xh, bf16* __restrict__ xl,
             const float* __restrict__ beta, int bidx, int kth)
{
    __shared__ int wsum[8];
    const int tid = threadIdx.x, wid = tid >> 5, lane = tid & 31;
    float* row = x + (size_t)blockIdx.x * NDIM;
    const int e0 = tid * 8;

    float e[8];
    float4 a = *reinterpret_cast<const float4*>(row + e0);
    float4 b4 = *reinterpret_cast<const float4*>(row + e0 + 4);
    e[0]=a.x; e[1]=a.y; e[2]=a.z; e[3]=a.w; e[4]=b4.x; e[5]=b4.y; e[6]=b4.z; e[7]=b4.w;
    uint32_t k[8];
    #pragma unroll
    for (int i = 0; i < 8; i++) k[i] = __float_as_uint(fabsf(e[i]));

    uint32_t thr = 0;
    for (int bit = 30; bit >= 0; bit--) {
        uint32_t cand = thr | (1u << bit);
        int c = 0;
        #pragma unroll
        for (int i = 0; i < 8; i++) c += (k[i] >= cand);
        c = __reduce_add_sync(0xFFFFFFFFu, c);
        if (lane == 0) wsum[wid] = c;
        __syncthreads();
        int tot = wsum[0]+wsum[1]+wsum[2]+wsum[3]+wsum[4]+wsum[5]+wsum[6]+wsum[7];
        if (tot >= kth) thr = cand;
        __syncthreads();
    }

    const float thf = __uint_as_float(thr);
    const float b = beta[bidx];
    float r[8];
    #pragma unroll
    for (int i = 0; i < 8; i++) {
        float val = e[i];
        float u = val / b;
        float soft = b * copysignf(fmaxf(fabsf(u) - 1.0f, 0.0f), u);
        r[i] = (fabsf(val) >= thf) ? val : soft;
    }
    *reinterpret_cast<float4*>(row + e0)     = make_float4(r[0], r[1], r[2], r[3]);
    *reinterpret_cast<float4*>(row + e0 + 4) = make_float4(r[4], r[5], r[6], r[7]);

    const size_t go = (size_t)blockIdx.x * NDIM + e0;
    #pragma unroll
    for (int i = 0; i < 8; i += 2) {
        bf16 h0 = __float2bfloat16(r[i]), h1 = __float2bfloat16(r[i+1]);
        __nv_bfloat162 hp{h0, h1};
        __nv_bfloat162 lp{__float2bfloat16(r[i]   - __bfloat162float(h0)),
                          __float2bfloat16(r[i+1] - __bfloat162float(h1))};
        *reinterpret_cast<__nv_bfloat162*>(xh + go + i) = hp;
        *reinterpret_cast<__nv_bfloat162*>(xl + go + i) = lp;
    }
}

// ---------------------------------------------------------------------------
extern "C" void kernel_launch(void* const* d_in, const int* in_sizes, int n_in,
                              void* d_out, int out_size)
{
    const float* y    = (const float*)d_in[0];   // [8192, 512]
    const float* A    = (const float*)d_in[1];   // [512, 2048]
    const float* W    = (const float*)d_in[2];   // [2048, 512] = A^T
    const float* beta = (const float*)d_in[3];
    const float* mu   = (const float*)d_in[4];
    float* x = (float*)d_out;                    // [8192, 2048]

    cudaFuncSetAttribute(mma_gemm<0>, cudaFuncAttributeMaxDynamicSharedMemorySize, SMEM_B);
    cudaFuncSetAttribute(mma_gemm<1>, cudaFuncAttributeMaxDynamicSharedMemorySize, SMEM_B);
    cudaFuncSetAttribute(mma_gemm<2>, cudaFuncAttributeMaxDynamicSharedMemorySize, SMEM_B);

    bf16 *xh, *xl, *rh, *rl, *yh, *yl, *Ahp, *Alp, *Wh, *Wl;
    { void* p; cudaGetSymbolAddress(&p, g_xh); xh = (bf16*)p; }
    { void* p; cudaGetSymbolAddress(&p, g_xl); xl = (bf16*)p; }
    { void* p; cudaGetSymbolAddress(&p, g_rh); rh = (bf16*)p; }
    { void* p; cudaGetSymbolAddress(&p, g_rl); rl = (bf16*)p; }
    { void* p; cudaGetSymbolAddress(&p, g_yh); yh = (bf16*)p; }
    { void* p; cudaGetSymbolAddress(&p, g_yl); yl = (bf16*)p; }
    { void* p; cudaGetSymbolAddress(&p, g_Ah); Ahp = (bf16*)p; }
    { void* p; cudaGetSymbolAddress(&p, g_Al); Alp = (bf16*)p; }
    { void* p; cudaGetSymbolAddress(&p, g_Wh); Wh = (bf16*)p; }
    { void* p; cudaGetSymbolAddress(&p, g_Wl); Wl = (bf16*)p; }

    // splits of inputs
    {
        int n4 = BATCH * MDIM / 4;
        split_kernel<<<(n4 + 255) / 256, 256>>>(y, yh, yl, n4);
        n4 = MDIM * NDIM / 4;
        split_kernel<<<(n4 + 255) / 256, 256>>>(A, Ahp, Alp, n4);
        split_kernel<<<(n4 + 255) / 256, 256>>>(W, Wh, Wl, n4);
    }

    const dim3 blk(256);
    const dim3 gN(BATCH / 128, NDIM / 128);   // (64, 16)
    const dim3 gM(BATCH / 128, MDIM / 128);   // (64, 4)
    const int kth[6] = {0, 24, 49, 73, 98, 122};

    // x0 = mu0 * (y @ A):  X = y (K=512), B = W rows ([N,K]), P=2048
    mma_gemm<0><<<gN, blk, SMEM_B>>>(yh, yl, Wh, Wl, MDIM, NDIM,
                                     x, xh, xl, nullptr, mu, 0);

    for (int t = 1; t <= 5; t++) {
        // r = x @ A.T - y:  X = x (K=2048), B = A rows ([M,N] K-major over N), P=512
        mma_gemm<1><<<gM, blk, SMEM_B>>>(xh, xl, Ahp, Alp, NDIM, MDIM,
                                         nullptr, rh, rl, y, mu, t);
        // v = x - mu*(r @ W.T):  X = r (K=512), B = W rows, P=2048  (in-place on x)
        mma_gemm<2><<<gN, blk, SMEM_B>>>(rh, rl, Wh, Wl, MDIM, NDIM,
                                         x, nullptr, nullptr, x, mu, t);
        // x = shrink(v)
        shrink2<<<BATCH, blk>>>(x, xh, xl, beta, t, kth[t]);
    }
}

// round 4
// speedup vs baseline: 3.3621x; 1.0174x over previous
#include <cuda_runtime.h>
#include <cuda_bf16.h>
#include <cstdint>

#define BATCH 8192
#define MDIM  512
#define NDIM  2048

typedef __nv_bfloat16 bf16;

// ---------------- static device scratch (no allocs allowed) ----------------
__device__ __align__(256) bf16 g_xh[(size_t)BATCH * NDIM];
__device__ __align__(256) bf16 g_xl[(size_t)BATCH * NDIM];
__device__ __align__(256) bf16 g_rh[(size_t)BATCH * MDIM];
__device__ __align__(256) bf16 g_rl[(size_t)BATCH * MDIM];
__device__ __align__(256) bf16 g_yh[(size_t)BATCH * MDIM];
__device__ __align__(256) bf16 g_yl[(size_t)BATCH * MDIM];
__device__ __align__(256) bf16 g_Ah[(size_t)MDIM * NDIM];
__device__ __align__(256) bf16 g_Al[(size_t)MDIM * NDIM];
__device__ __align__(256) bf16 g_Wh[(size_t)NDIM * MDIM];
__device__ __align__(256) bf16 g_Wl[(size_t)NDIM * MDIM];

// ---------------- PTX helpers (base-ISA only) ----------------
__device__ __forceinline__ uint32_t smem_u32(const void* p) {
    uint32_t a;
    asm("{ .reg .u64 t; cvta.to.shared.u64 t, %1; cvt.u32.u64 %0, t; }" : "=r"(a) : "l"(p));
    return a;
}
__device__ __forceinline__ void cpa16(uint32_t dst, const void* src) {
    asm volatile("cp.async.cg.shared.global [%0], [%1], 16;" :: "r"(dst), "l"(src));
}
__device__ __forceinline__ void cpa_commit() { asm volatile("cp.async.commit_group;" ::: "memory"); }
template<int N> __device__ __forceinline__ void cpa_wait() {
    asm volatile("cp.async.wait_group %0;" :: "n"(N) : "memory");
}
__device__ __forceinline__ void ldm_x4(uint32_t* r, uint32_t addr) {
    asm volatile("ldmatrix.sync.aligned.m8n8.x4.shared.b16 {%0,%1,%2,%3}, [%4];"
        : "=r"(r[0]), "=r"(r[1]), "=r"(r[2]), "=r"(r[3]) : "r"(addr));
}
__device__ __forceinline__ void mma_bf16(float* d, const uint32_t* a, const uint32_t* b) {
    asm volatile("mma.sync.aligned.m16n8k16.row.col.f32.bf16.bf16.f32 "
        "{%0,%1,%2,%3}, {%4,%5,%6,%7}, {%8,%9}, {%0,%1,%2,%3};"
        : "+f"(d[0]), "+f"(d[1]), "+f"(d[2]), "+f"(d[3])
        : "r"(a[0]), "r"(a[1]), "r"(a[2]), "r"(a[3]), "r"(b[0]), "r"(b[1]));
}

// ---------------- fp32 -> bf16 hi/lo split ----------------
__global__ void split_kernel(const float* __restrict__ s, bf16* __restrict__ h,
                             bf16* __restrict__ l, int n4) {
    int i = blockIdx.x * 256 + threadIdx.x;
    if (i >= n4) return;
    float4 v = reinterpret_cast<const float4*>(s)[i];
    bf16 h0 = __float2bfloat16(v.x), h1 = __float2bfloat16(v.y);
    bf16 h2 = __float2bfloat16(v.z), h3 = __float2bfloat16(v.w);
    __nv_bfloat162 hp0{h0, h1}, hp1{h2, h3};
    __nv_bfloat162 lp0{__float2bfloat16(v.x - __bfloat162float(h0)),
                       __float2bfloat16(v.y - __bfloat162float(h1))};
    __nv_bfloat162 lp1{__float2bfloat16(v.z - __bfloat162float(h2)),
                       __float2bfloat16(v.w - __bfloat162float(h3))};
    reinterpret_cast<__nv_bfloat162*>(h)[i * 2 + 0] = hp0;
    reinterpret_cast<__nv_bfloat162*>(h)[i * 2 + 1] = hp1;
    reinterpret_cast<__nv_bfloat162*>(l)[i * 2 + 0] = lp0;
    reinterpret_cast<__nv_bfloat162*>(l)[i * 2 + 1] = lp1;
}

// ---------------- HMMA split-bf16 GEMM ----------------
// C[b,p] = sum_k X[b,k]*Wm[p,k]  (both K-major). 3-product split: hh + hl + lh.
// MODE 0: f = mu*acc         -> outf + splits
// MODE 1: f = acc - aux      -> splits only
// MODE 2: f = aux - mu*acc   -> outf only
#define PITCH 80                       // 32 bf16 (64B) + 16B pad per row
#define TILE_B (128 * PITCH)           // 10240 B per tile
#define STAGE_B (4 * TILE_B)           // Xh, Xl, Wh, Wl = 40960 B
#define NSTAGE 4
#define SMEM_B (NSTAGE * STAGE_B)      // 163840 B

template<int MODE>
__global__ __launch_bounds__(256, 1)
void mma_gemm(const bf16* __restrict__ Xh, const bf16* __restrict__ Xl,
              const bf16* __restrict__ Bh, const bf16* __restrict__ Bl,
              int K, int P,
              float* __restrict__ outf, bf16* __restrict__ outh, bf16* __restrict__ outl,
              const float* __restrict__ aux, const float* __restrict__ mu, int muidx)
{
    extern __shared__ char smem[];
    const uint32_t sb = smem_u32(smem);
    const int tid = threadIdx.x, lane = tid & 31, wid = tid >> 5;
    const int wr = wid >> 2, wc = wid & 3;          // 2x4 warp grid
    const int b0 = blockIdx.x * 128, p0 = blockIdx.y * 128;

    float acc[4][4][4];
    #pragma unroll
    for (int i = 0; i < 4; i++)
        #pragma unroll
        for (int j = 0; j < 4; j++)
            #pragma unroll
            for (int q = 0; q < 4; q++) acc[i][j][q] = 0.f;

    const int nch = K >> 5;   // KC = 32

    auto load_stage = [&](int s, int c) {
        const int k0 = c * 32;
        const uint32_t st = sb + s * STAGE_B;
        const bf16* srcs[4] = { Xh + (size_t)b0 * K + k0, Xl + (size_t)b0 * K + k0,
                                Bh + (size_t)p0 * K + k0, Bl + (size_t)p0 * K + k0 };
        #pragma unroll
        for (int t = 0; t < 4; t++) {
            const uint32_t tb = st + t * TILE_B;
            const bf16* g = srcs[t];
            #pragma unroll
            for (int l = 0; l < 2; l++) {
                int id = tid + l * 256;               // 0..511
                int row = id >> 2, ch = id & 3;
                cpa16(tb + row * PITCH + ch * 16, g + (size_t)row * K + ch * 8);
            }
        }
        cpa_commit();
    };

    load_stage(0, 0);
    load_stage(1, 1);
    load_stage(2, 2);

    for (int c = 0; c < nch; c++) {
        const int s = c & (NSTAGE - 1);
        cpa_wait<2>();
        __syncthreads();
        if (c + 3 < nch) load_stage((c + 3) & (NSTAGE - 1), c + 3);

        const uint32_t xs = sb + s * STAGE_B;
        const uint32_t ws = xs + 2 * TILE_B;
        #pragma unroll
        for (int ks = 0; ks < 2; ks++) {
            const int kb = ks * 32;                  // byte offset of k16 step
            uint32_t ah[4][4], al[4][4], bh[4][2], bl[4][2];
            #pragma unroll
            for (int mi = 0; mi < 4; mi++) {
                uint32_t a = xs + (uint32_t)(wr * 64 + mi * 16 + (lane & 15)) * PITCH
                           + kb + ((lane >> 4) << 4);
                ldm_x4(ah[mi], a);
                ldm_x4(al[mi], a + TILE_B);
            }
            // B: pack two n-tiles (ni, ni+1) per ldmatrix.x4
            #pragma unroll
            for (int nb = 0; nb < 2; nb++) {
                uint32_t a = ws + (uint32_t)(wc * 32 + nb * 16 + ((lane >> 4) << 3)
                           + (lane & 7)) * PITCH
                           + kb + (((lane >> 3) & 1) << 4);
                uint32_t r4[4];
                ldm_x4(r4, a);
                bh[nb*2][0] = r4[0]; bh[nb*2][1] = r4[1];
                bh[nb*2+1][0] = r4[2]; bh[nb*2+1][1] = r4[3];
                ldm_x4(r4, a + TILE_B);
                bl[nb*2][0] = r4[0]; bl[nb*2][1] = r4[1];
                bl[nb*2+1][0] = r4[2]; bl[nb*2+1][1] = r4[3];
            }
            // Three sweeps: consecutive MMAs hit different accumulators (no RAW chain)
            #pragma unroll
            for (int mi = 0; mi < 4; mi++)
                #pragma unroll
                for (int ni = 0; ni < 4; ni++)
                    mma_bf16(acc[mi][ni], ah[mi], bh[ni]);
            #pragma unroll
            for (int mi = 0; mi < 4; mi++)
                #pragma unroll
                for (int ni = 0; ni < 4; ni++)
                    mma_bf16(acc[mi][ni], ah[mi], bl[ni]);
            #pragma unroll
            for (int mi = 0; mi < 4; mi++)
                #pragma unroll
                for (int ni = 0; ni < 4; ni++)
                    mma_bf16(acc[mi][ni], al[mi], bh[ni]);
        }
    }

    // ---------------- epilogue ----------------
    const float m = (MODE != 1) ? __ldg(mu + muidx) : 0.f;
    const int rbase = b0 + wr * 64 + (lane >> 2);
    const int cbase = p0 + wc * 32 + (lane & 3) * 2;

    #pragma unroll
    for (int mi = 0; mi < 4; mi++) {
        #pragma unroll
        for (int h = 0; h < 2; h++) {
            const int row = rbase + mi * 16 + h * 8;
            #pragma unroll
            for (int ni = 0; ni < 4; ni++) {
                const size_t off = (size_t)row * P + cbase + ni * 8;
                float v0 = acc[mi][ni][h * 2], v1 = acc[mi][ni][h * 2 + 1];
                if (MODE == 0) { v0 *= m; v1 *= m; }
                else {
                    float2 a2 = *reinterpret_cast<const float2*>(aux + off);
                    if (MODE == 1) { v0 -= a2.x; v1 -= a2.y; }
                    else { v0 = a2.x - m * v0; v1 = a2.y - m * v1; }
                }
                if (MODE == 0 || MODE == 2)
                    *reinterpret_cast<float2*>(outf + off) = make_float2(v0, v1);
                if (MODE == 0 || MODE == 1) {
                    bf16 h0 = __float2bfloat16(v0), h1 = __float2bfloat16(v1);
                    __nv_bfloat162 hp{h0, h1};
                    __nv_bfloat162 lp{__float2bfloat16(v0 - __bfloat162float(h0)),
                                      __float2bfloat16(v1 - __bfloat162float(h1))};
                    *reinterpret_cast<__nv_bfloat162*>(outh + off) = hp;
                    *reinterpret_cast<__nv_bfloat162*>(outl + off) = lp;
                }
            }
        }
    }
}

// ---------------- shrink: exact kth-largest via bitwise binary search ----------------
__global__ __launch_bounds__(256, 4)
void shrink2(float* __restrict__ x, bf16* __restrict__ xh, bf16* __restrict__ xl,
             const float* __restrict__ beta, int bidx, int kth)
{
    __shared__ int wsum[2][8];
    const int tid = threadIdx.x, wid = tid >> 5, lane = tid & 31;
    float* row = x + (size_t)blockIdx.x * NDIM;
    const int e0 = tid * 8;

    float e[8];
    float4 a = *reinterpret_cast<const float4*>(row + e0);
    float4 b4 = *reinterpret_cast<const float4*>(row + e0 + 4);
    e[0]=a.x; e[1]=a.y; e[2]=a.z; e[3]=a.w; e[4]=b4.x; e[5]=b4.y; e[6]=b4.z; e[7]=b4.w;
    uint32_t k[8];
    #pragma unroll
    for (int i = 0; i < 8; i++) k[i] = __float_as_uint(fabsf(e[i]));

    uint32_t thr = 0;
    for (int bit = 30; bit >= 0; bit--) {
        uint32_t cand = thr | (1u << bit);
        int c = 0;
        #pragma unroll
        for (int i = 0; i < 8; i++) c += (k[i] >= cand);
        c = __reduce_add_sync(0xFFFFFFFFu, c);
        const int buf = bit & 1;
        if (lane == 0) wsum[buf][wid] = c;
        __syncthreads();
        int tot = wsum[buf][0]+wsum[buf][1]+wsum[buf][2]+wsum[buf][3]
                + wsum[buf][4]+wsum[buf][5]+wsum[buf][6]+wsum[buf][7];
        if (tot >= kth) thr = cand;
    }

    const float thf = __uint_as_float(thr);
    const float b = beta[bidx];
    float r[8];
    #pragma unroll
    for (int i = 0; i < 8; i++) {
        float val = e[i];
        float u = val / b;
        float soft = b * copysignf(fmaxf(fabsf(u) - 1.0f, 0.0f), u);
        r[i] = (fabsf(val) >= thf) ? val : soft;
    }
    *reinterpret_cast<float4*>(row + e0)     = make_float4(r[0], r[1], r[2], r[3]);
    *reinterpret_cast<float4*>(row + e0 + 4) = make_float4(r[4], r[5], r[6], r[7]);

    const size_t go = (size_t)blockIdx.x * NDIM + e0;
    #pragma unroll
    for (int i = 0; i < 8; i += 2) {
        bf16 h0 = __float2bfloat16(r[i]), h1 = __float2bfloat16(r[i+1]);
        __nv_bfloat162 hp{h0, h1};
        __nv_bfloat162 lp{__float2bfloat16(r[i]   - __bfloat162float(h0)),
                          __float2bfloat16(r[i+1] - __bfloat162float(h1))};
        *reinterpret_cast<__nv_bfloat162*>(xh + go + i) = hp;
        *reinterpret_cast<__nv_bfloat162*>(xl + go + i) = lp;
    }
}

// ---------------------------------------------------------------------------
extern "C" void kernel_launch(void* const* d_in, const int* in_sizes, int n_in,
                              void* d_out, int out_size)
{
    const float* y    = (const float*)d_in[0];   // [8192, 512]
    const float* A    = (const float*)d_in[1];   // [512, 2048]
    const float* W    = (const float*)d_in[2];   // [2048, 512] = A^T
    const float* beta = (const float*)d_in[3];
    const float* mu   = (const float*)d_in[4];
    float* x = (float*)d_out;                    // [8192, 2048]

    cudaFuncSetAttribute(mma_gemm<0>, cudaFuncAttributeMaxDynamicSharedMemorySize, SMEM_B);
    cudaFuncSetAttribute(mma_gemm<1>, cudaFuncAttributeMaxDynamicSharedMemorySize, SMEM_B);
    cudaFuncSetAttribute(mma_gemm<2>, cudaFuncAttributeMaxDynamicSharedMemorySize, SMEM_B);

    bf16 *xh, *xl, *rh, *rl, *yh, *yl, *Ahp, *Alp, *Wh, *Wl;
    { void* p; cudaGetSymbolAddress(&p, g_xh); xh = (bf16*)p; }
    { void* p; cudaGetSymbolAddress(&p, g_xl); xl = (bf16*)p; }
    { void* p; cudaGetSymbolAddress(&p, g_rh); rh = (bf16*)p; }
    { void* p; cudaGetSymbolAddress(&p, g_rl); rl = (bf16*)p; }
    { void* p; cudaGetSymbolAddress(&p, g_yh); yh = (bf16*)p; }
    { void* p; cudaGetSymbolAddress(&p, g_yl); yl = (bf16*)p; }
    { void* p; cudaGetSymbolAddress(&p, g_Ah); Ahp = (bf16*)p; }
    { void* p; cudaGetSymbolAddress(&p, g_Al); Alp = (bf16*)p; }
    { void* p; cudaGetSymbolAddress(&p, g_Wh); Wh = (bf16*)p; }
    { void* p; cudaGetSymbolAddress(&p, g_Wl); Wl = (bf16*)p; }

    // splits of inputs
    {
        int n4 = BATCH * MDIM / 4;
        split_kernel<<<(n4 + 255) / 256, 256>>>(y, yh, yl, n4);
        n4 = MDIM * NDIM / 4;
        split_kernel<<<(n4 + 255) / 256, 256>>>(A, Ahp, Alp, n4);
        split_kernel<<<(n4 + 255) / 256, 256>>>(W, Wh, Wl, n4);
    }

    const dim3 blk(256);
    const dim3 gN(BATCH / 128, NDIM / 128);   // (64, 16)
    const dim3 gM(BATCH / 128, MDIM / 128);   // (64, 4)
    const int kth[6] = {0, 24, 49, 73, 98, 122};

    // x0 = mu0 * (y @ A):  X = y (K=512), B = W rows ([N,K]), P=2048
    mma_gemm<0><<<gN, blk, SMEM_B>>>(yh, yl, Wh, Wl, MDIM, NDIM,
                                     x, xh, xl, nullptr, mu, 0);

    for (int t = 1; t <= 5; t++) {
        // r = x @ A.T - y:  X = x (K=2048), B = A rows, P=512
        mma_gemm<1><<<gM, blk, SMEM_B>>>(xh, xl, Ahp, Alp, NDIM, MDIM,
                                         nullptr, rh, rl, y, mu, t);
        // v = x - mu*(r @ W.T):  X = r (K=512), B = W rows, P=2048 (in-place on x)
        mma_gemm<2><<<gN, blk, SMEM_B>>>(rh, rl, Wh, Wl, MDIM, NDIM,
                                         x, nullptr, nullptr, x, mu, t);
        // x = shrink(v)
        shrink2<<<BATCH, blk>>>(x, xh, xl, beta, t, kth[t]);
    }
}

// round 5
// speedup vs baseline: 3.5853x; 1.0664x over previous
#include <cuda_runtime.h>
#include <cuda_bf16.h>
#include <cstdint>

#define BATCH 8192
#define MDIM  512
#define NDIM  2048

typedef __nv_bfloat16 bf16;

// ---------------- static device scratch (no allocs allowed) ----------------
__device__ __align__(256) bf16 g_xh[(size_t)BATCH * NDIM];
__device__ __align__(256) bf16 g_xl[(size_t)BATCH * NDIM];
__device__ __align__(256) bf16 g_rh[(size_t)BATCH * MDIM];
__device__ __align__(256) bf16 g_rl[(size_t)BATCH * MDIM];
__device__ __align__(256) bf16 g_yh[(size_t)BATCH * MDIM];
__device__ __align__(256) bf16 g_yl[(size_t)BATCH * MDIM];
__device__ __align__(256) bf16 g_Ah[(size_t)MDIM * NDIM];
__device__ __align__(256) bf16 g_Al[(size_t)MDIM * NDIM];
__device__ __align__(256) bf16 g_Wh[(size_t)NDIM * MDIM];
__device__ __align__(256) bf16 g_Wl[(size_t)NDIM * MDIM];

// ---------------- PTX helpers (base-ISA only) ----------------
__device__ __forceinline__ uint32_t smem_u32(const void* p) {
    uint32_t a;
    asm("{ .reg .u64 t; cvta.to.shared.u64 t, %1; cvt.u32.u64 %0, t; }" : "=r"(a) : "l"(p));
    return a;
}
__device__ __forceinline__ void cpa16(uint32_t dst, const void* src) {
    asm volatile("cp.async.cg.shared.global [%0], [%1], 16;" :: "r"(dst), "l"(src));
}
__device__ __forceinline__ void cpa_commit() { asm volatile("cp.async.commit_group;" ::: "memory"); }
template<int N> __device__ __forceinline__ void cpa_wait() {
    asm volatile("cp.async.wait_group %0;" :: "n"(N) : "memory");
}
__device__ __forceinline__ void ldm_x4(uint32_t* r, uint32_t addr) {
    asm volatile("ldmatrix.sync.aligned.m8n8.x4.shared.b16 {%0,%1,%2,%3}, [%4];"
        : "=r"(r[0]), "=r"(r[1]), "=r"(r[2]), "=r"(r[3]) : "r"(addr));
}
__device__ __forceinline__ void mma_bf16(float* d, const uint32_t* a, const uint32_t* b) {
    asm volatile("mma.sync.aligned.m16n8k16.row.col.f32.bf16.bf16.f32 "
        "{%0,%1,%2,%3}, {%4,%5,%6,%7}, {%8,%9}, {%0,%1,%2,%3};"
        : "+f"(d[0]), "+f"(d[1]), "+f"(d[2]), "+f"(d[3])
        : "r"(a[0]), "r"(a[1]), "r"(a[2]), "r"(a[3]), "r"(b[0]), "r"(b[1]));
}

// ---------------- fp32 -> bf16 hi/lo split ----------------
__global__ void split_kernel(const float* __restrict__ s, bf16* __restrict__ h,
                             bf16* __restrict__ l, int n4) {
    int i = blockIdx.x * 256 + threadIdx.x;
    if (i >= n4) return;
    float4 v = reinterpret_cast<const float4*>(s)[i];
    bf16 h0 = __float2bfloat16(v.x), h1 = __float2bfloat16(v.y);
    bf16 h2 = __float2bfloat16(v.z), h3 = __float2bfloat16(v.w);
    __nv_bfloat162 hp0{h0, h1}, hp1{h2, h3};
    __nv_bfloat162 lp0{__float2bfloat16(v.x - __bfloat162float(h0)),
                       __float2bfloat16(v.y - __bfloat162float(h1))};
    __nv_bfloat162 lp1{__float2bfloat16(v.z - __bfloat162float(h2)),
                       __float2bfloat16(v.w - __bfloat162float(h3))};
    reinterpret_cast<__nv_bfloat162*>(h)[i * 2 + 0] = hp0;
    reinterpret_cast<__nv_bfloat162*>(h)[i * 2 + 1] = hp1;
    reinterpret_cast<__nv_bfloat162*>(l)[i * 2 + 0] = lp0;
    reinterpret_cast<__nv_bfloat162*>(l)[i * 2 + 1] = lp1;
}

// ---------------- HMMA split-bf16 GEMM (2 CTA/SM variant) ----------------
// C[b,p] = sum_k X[b,k]*Wm[p,k]  (both K-major). 3-product split: hh + hl + lh.
// MODE 0: f = mu*acc         -> outf + splits
// MODE 1: f = acc - aux      -> splits only
// MODE 2: f = aux - mu*acc   -> outf only
#define PITCH 80                       // 32 bf16 (64B) + 16B pad per row
#define TILE_B (128 * PITCH)           // 10240 B per tile
#define STAGE_B (4 * TILE_B)           // Xh, Xl, Wh, Wl = 40960 B
#define NSTAGE 2
#define SMEM_B (NSTAGE * STAGE_B)      // 81920 B -> two CTAs per SM

template<int MODE>
__global__ __launch_bounds__(256, 2)
void mma_gemm(const bf16* __restrict__ Xh, const bf16* __restrict__ Xl,
              const bf16* __restrict__ Bh, const bf16* __restrict__ Bl,
              int K, int P,
              float* __restrict__ outf, bf16* __restrict__ outh, bf16* __restrict__ outl,
              const float* __restrict__ aux, const float* __restrict__ mu, int muidx)
{
    extern __shared__ char smem[];
    const uint32_t sb = smem_u32(smem);
    const int tid = threadIdx.x, lane = tid & 31, wid = tid >> 5;
    const int wr = wid >> 2, wc = wid & 3;          // 2x4 warp grid
    const int b0 = blockIdx.x * 128, p0 = blockIdx.y * 128;

    float acc[4][4][4];
    #pragma unroll
    for (int i = 0; i < 4; i++)
        #pragma unroll
        for (int j = 0; j < 4; j++)
            #pragma unroll
            for (int q = 0; q < 4; q++) acc[i][j][q] = 0.f;

    const int nch = K >> 5;   // KC = 32

    auto load_stage = [&](int s, int c) {
        const int k0 = c * 32;
        const uint32_t st = sb + s * STAGE_B;
        const bf16* srcs[4] = { Xh + (size_t)b0 * K + k0, Xl + (size_t)b0 * K + k0,
                                Bh + (size_t)p0 * K + k0, Bl + (size_t)p0 * K + k0 };
        #pragma unroll
        for (int t = 0; t < 4; t++) {
            const uint32_t tb = st + t * TILE_B;
            const bf16* g = srcs[t];
            #pragma unroll
            for (int l = 0; l < 2; l++) {
                int id = tid + l * 256;               // 0..511
                int row = id >> 2, ch = id & 3;
                cpa16(tb + row * PITCH + ch * 16, g + (size_t)row * K + ch * 8);
            }
        }
        cpa_commit();
    };

    load_stage(0, 0);
    if (nch > 1) load_stage(1, 1);

    for (int c = 0; c < nch; c++) {
        const int s = c & 1;
        if (c + 1 < nch) cpa_wait<1>(); else cpa_wait<0>();
        __syncthreads();

        const uint32_t xs = sb + s * STAGE_B;
        const uint32_t ws = xs + 2 * TILE_B;
        #pragma unroll
        for (int ks = 0; ks < 2; ks++) {
            const int kb = ks * 32;                  // byte offset of k16 step
            uint32_t ah[4][4], al[4][4];
            #pragma unroll
            for (int mi = 0; mi < 4; mi++) {
                uint32_t a = xs + (uint32_t)(wr * 64 + mi * 16 + (lane & 15)) * PITCH
                           + kb + ((lane >> 4) << 4);
                ldm_x4(ah[mi], a);
                ldm_x4(al[mi], a + TILE_B);
            }
            // B fragments loaded per n-pair to keep live registers low
            #pragma unroll
            for (int nb = 0; nb < 2; nb++) {
                uint32_t a = ws + (uint32_t)(wc * 32 + nb * 16 + ((lane >> 4) << 3)
                           + (lane & 7)) * PITCH
                           + kb + (((lane >> 3) & 1) << 4);
                uint32_t bh[4], bl[4];               // two n-tiles (2 regs each)
                ldm_x4(bh, a);
                ldm_x4(bl, a + TILE_B);
                // three product sweeps over 8 accumulators (no RAW chains)
                #pragma unroll
                for (int mi = 0; mi < 4; mi++) {
                    mma_bf16(acc[mi][nb*2],   ah[mi], bh);
                    mma_bf16(acc[mi][nb*2+1], ah[mi], bh + 2);
                }
                #pragma unroll
                for (int mi = 0; mi < 4; mi++) {
                    mma_bf16(acc[mi][nb*2],   ah[mi], bl);
                    mma_bf16(acc[mi][nb*2+1], ah[mi], bl + 2);
                }
                #pragma unroll
                for (int mi = 0; mi < 4; mi++) {
                    mma_bf16(acc[mi][nb*2],   al[mi], bh);
                    mma_bf16(acc[mi][nb*2+1], al[mi], bh + 2);
                }
            }
        }
        __syncthreads();
        if (c + 2 < nch) load_stage(s, c + 2);
    }

    // ---------------- epilogue ----------------
    const float m = (MODE != 1) ? __ldg(mu + muidx) : 0.f;
    const int rbase = b0 + wr * 64 + (lane >> 2);
    const int cbase = p0 + wc * 32 + (lane & 3) * 2;

    #pragma unroll
    for (int mi = 0; mi < 4; mi++) {
        #pragma unroll
        for (int h = 0; h < 2; h++) {
            const int row = rbase + mi * 16 + h * 8;
            #pragma unroll
            for (int ni = 0; ni < 4; ni++) {
                const size_t off = (size_t)row * P + cbase + ni * 8;
                float v0 = acc[mi][ni][h * 2], v1 = acc[mi][ni][h * 2 + 1];
                if (MODE == 0) { v0 *= m; v1 *= m; }
                else {
                    float2 a2 = *reinterpret_cast<const float2*>(aux + off);
                    if (MODE == 1) { v0 -= a2.x; v1 -= a2.y; }
                    else { v0 = a2.x - m * v0; v1 = a2.y - m * v1; }
                }
                if (MODE == 0 || MODE == 2)
                    *reinterpret_cast<float2*>(outf + off) = make_float2(v0, v1);
                if (MODE == 0 || MODE == 1) {
                    bf16 h0 = __float2bfloat16(v0), h1 = __float2bfloat16(v1);
                    __nv_bfloat162 hp{h0, h1};
                    __nv_bfloat162 lp{__float2bfloat16(v0 - __bfloat162float(h0)),
                                      __float2bfloat16(v1 - __bfloat162float(h1))};
                    *reinterpret_cast<__nv_bfloat162*>(outh + off) = hp;
                    *reinterpret_cast<__nv_bfloat162*>(outl + off) = lp;
                }
            }
        }
    }
}

// ---------------- shrink: exact kth-largest via bitwise binary search ----------------
__global__ __launch_bounds__(256, 4)
void shrink2(float* __restrict__ x, bf16* __restrict__ xh, bf16* __restrict__ xl,
             const float* __restrict__ beta, int bidx, int kth)
{
    __shared__ int wsum[2][8];
    const int tid = threadIdx.x, wid = tid >> 5, lane = tid & 31;
    float* row = x + (size_t)blockIdx.x * NDIM;
    const int e0 = tid * 8;

    float e[8];
    float4 a = *reinterpret_cast<const float4*>(row + e0);
    float4 b4 = *reinterpret_cast<const float4*>(row + e0 + 4);
    e[0]=a.x; e[1]=a.y; e[2]=a.z; e[3]=a.w; e[4]=b4.x; e[5]=b4.y; e[6]=b4.z; e[7]=b4.w;
    uint32_t k[8];
    #pragma unroll
    for (int i = 0; i < 8; i++) k[i] = __float_as_uint(fabsf(e[i]));

    uint32_t thr = 0;
    for (int bit = 30; bit >= 0; bit--) {
        uint32_t cand = thr | (1u << bit);
        int c = 0;
        #pragma unroll
        for (int i = 0; i < 8; i++) c += (k[i] >= cand);
        c = __reduce_add_sync(0xFFFFFFFFu, c);
        const int buf = bit & 1;
        if (lane == 0) wsum[buf][wid] = c;
        __syncthreads();
        int tot = wsum[buf][0]+wsum[buf][1]+wsum[buf][2]+wsum[buf][3]
                + wsum[buf][4]+wsum[buf][5]+wsum[buf][6]+wsum[buf][7];
        if (tot >= kth) thr = cand;
    }

    const float thf = __uint_as_float(thr);
    const float b = beta[bidx];
    float r[8];
    #pragma unroll
    for (int i = 0; i < 8; i++) {
        float val = e[i];
        float u = val / b;
        float soft = b * copysignf(fmaxf(fabsf(u) - 1.0f, 0.0f), u);
        r[i] = (fabsf(val) >= thf) ? val : soft;
    }
    *reinterpret_cast<float4*>(row + e0)     = make_float4(r[0], r[1], r[2], r[3]);
    *reinterpret_cast<float4*>(row + e0 + 4) = make_float4(r[4], r[5], r[6], r[7]);

    const size_t go = (size_t)blockIdx.x * NDIM + e0;
    #pragma unroll
    for (int i = 0; i < 8; i += 2) {
        bf16 h0 = __float2bfloat16(r[i]), h1 = __float2bfloat16(r[i+1]);
        __nv_bfloat162 hp{h0, h1};
        __nv_bfloat162 lp{__float2bfloat16(r[i]   - __bfloat162float(h0)),
                          __float2bfloat16(r[i+1] - __bfloat162float(h1))};
        *reinterpret_cast<__nv_bfloat162*>(xh + go + i) = hp;
        *reinterpret_cast<__nv_bfloat162*>(xl + go + i) = lp;
    }
}

// ---------------------------------------------------------------------------
extern "C" void kernel_launch(void* const* d_in, const int* in_sizes, int n_in,
                              void* d_out, int out_size)
{
    const float* y    = (const float*)d_in[0];   // [8192, 512]
    const float* A    = (const float*)d_in[1];   // [512, 2048]
    const float* W    = (const float*)d_in[2];   // [2048, 512] = A^T
    const float* beta = (const float*)d_in[3];
    const float* mu   = (const float*)d_in[4];
    float* x = (float*)d_out;                    // [8192, 2048]

    cudaFuncSetAttribute(mma_gemm<0>, cudaFuncAttributeMaxDynamicSharedMemorySize, SMEM_B);
    cudaFuncSetAttribute(mma_gemm<1>, cudaFuncAttributeMaxDynamicSharedMemorySize, SMEM_B);
    cudaFuncSetAttribute(mma_gemm<2>, cudaFuncAttributeMaxDynamicSharedMemorySize, SMEM_B);

    bf16 *xh, *xl, *rh, *rl, *yh, *yl, *Ahp, *Alp, *Wh, *Wl;
    { void* p; cudaGetSymbolAddress(&p, g_xh); xh = (bf16*)p; }
    { void* p; cudaGetSymbolAddress(&p, g_xl); xl = (bf16*)p; }
    { void* p; cudaGetSymbolAddress(&p, g_rh); rh = (bf16*)p; }
    { void* p; cudaGetSymbolAddress(&p, g_rl); rl = (bf16*)p; }
    { void* p; cudaGetSymbolAddress(&p, g_yh); yh = (bf16*)p; }
    { void* p; cudaGetSymbolAddress(&p, g_yl); yl = (bf16*)p; }
    { void* p; cudaGetSymbolAddress(&p, g_Ah); Ahp = (bf16*)p; }
    { void* p; cudaGetSymbolAddress(&p, g_Al); Alp = (bf16*)p; }
    { void* p; cudaGetSymbolAddress(&p, g_Wh); Wh = (bf16*)p; }
    { void* p; cudaGetSymbolAddress(&p, g_Wl); Wl = (bf16*)p; }

    // splits of inputs
    {
        int n4 = BATCH * MDIM / 4;
        split_kernel<<<(n4 + 255) / 256, 256>>>(y, yh, yl, n4);
        n4 = MDIM * NDIM / 4;
        split_kernel<<<(n4 + 255) / 256, 256>>>(A, Ahp, Alp, n4);
        split_kernel<<<(n4 + 255) / 256, 256>>>(W, Wh, Wl, n4);
    }

    const dim3 blk(256);
    const dim3 gN(BATCH / 128, NDIM / 128);   // (64, 16)
    const dim3 gM(BATCH / 128, MDIM / 128);   // (64, 4)
    const int kth[6] = {0, 24, 49, 73, 98, 122};

    // x0 = mu0 * (y @ A):  X = y (K=512), B = W rows ([N,K]), P=2048
    mma_gemm<0><<<gN, blk, SMEM_B>>>(yh, yl, Wh, Wl, MDIM, NDIM,
                                     x, xh, xl, nullptr, mu, 0);

    for (int t = 1; t <= 5; t++) {
        // r = x @ A.T - y:  X = x (K=2048), B = A rows, P=512
        mma_gemm<1><<<gM, blk, SMEM_B>>>(xh, xl, Ahp, Alp, NDIM, MDIM,
                                         nullptr, rh, rl, y, mu, t);
        // v = x - mu*(r @ W.T):  X = r (K=512), B = W rows, P=2048 (in-place on x)
        mma_gemm<2><<<gN, blk, SMEM_B>>>(rh, rl, Wh, Wl, MDIM, NDIM,
                                         x, nullptr, nullptr, x, mu, t);
        // x = shrink(v)
        shrink2<<<BATCH, blk>>>(x, xh, xl, beta, t, kth[t]);
    }
}